// round 3
// baseline (speedup 1.0000x reference)
#include <cuda_runtime.h>
#include <math.h>

// Problem constants
#define NROWS 8192
#define DIMS  256
#define EPS_F 1e-8f
#define ALPHA_D 1.5

// Tiling
#define BM 128          // tile rows/cols of the NxN matrix
#define BK 32           // k chunk
#define NTILES (NROWS / BM)   // 64

// Scratch (static device globals: allocation-free)
__device__ float  g_z1nT[DIMS * NROWS];   // normalized z1, TRANSPOSED: [k][i]
__device__ float  g_sq[NROWS];            // sum of squares of normalized rows (~1.0)
__device__ float  g_spos[NROWS];          // per-row positive-pair score
__device__ double g_neg;                  // off-diagonal exp sum accumulator

// ---------------------------------------------------------------------------
// helpers
// ---------------------------------------------------------------------------
__device__ __forceinline__ unsigned long long pack2(float x) {
    unsigned long long r;
    unsigned int u = __float_as_uint(x);
    asm("mov.b64 %0, {%1, %1};" : "=l"(r) : "r"(u));
    return r;
}

__device__ __forceinline__ void fma2(unsigned long long& d,
                                     unsigned long long a,
                                     unsigned long long b) {
    asm("fma.rn.f32x2 %0, %1, %2, %3;" : "=l"(d) : "l"(a), "l"(b), "l"(d));
}

__device__ __forceinline__ void unpack2(float& lo, float& hi, unsigned long long v) {
    unsigned int ulo, uhi;
    asm("mov.b64 {%0, %1}, %2;" : "=r"(ulo), "=r"(uhi) : "l"(v));
    lo = __uint_as_float(ulo);
    hi = __uint_as_float(uhi);
}

// block-wide sum over 256 threads, result broadcast to all threads
__device__ __forceinline__ float block_sum_256(float v, float* sbuf) {
    #pragma unroll
    for (int o = 16; o > 0; o >>= 1)
        v += __shfl_xor_sync(0xffffffffu, v, o);
    int w = threadIdx.x >> 5;
    if ((threadIdx.x & 31) == 0) sbuf[w] = v;
    __syncthreads();
    float s = 0.f;
    #pragma unroll
    for (int i = 0; i < 8; ++i) s += sbuf[i];
    __syncthreads();
    return s;
}

// ---------------------------------------------------------------------------
// kernel 0: zero the accumulator
// ---------------------------------------------------------------------------
__global__ void zero_kernel() { g_neg = 0.0; }

// ---------------------------------------------------------------------------
// kernel 1: normalize rows, write transposed z1n, sq, and per-row s_pos
// grid = NROWS blocks, 256 threads (== DIMS)
// ---------------------------------------------------------------------------
__global__ void prep_kernel(const float* __restrict__ z1,
                            const float* __restrict__ z2) {
    __shared__ float sbuf[8];
    int i = blockIdx.x;
    int t = threadIdx.x;

    float a = z1[i * DIMS + t];
    float b = z2[i * DIMS + t];

    float s1 = block_sum_256(a * a, sbuf);
    float s2 = block_sum_256(b * b, sbuf);

    float m1 = fmaxf(sqrtf(s1), 1e-12f);
    float m2 = fmaxf(sqrtf(s2), 1e-12f);
    float an = a / m1;
    float bn = b / m2;

    // transposed store: column i of row k=t (scattered, but tiny total traffic)
    g_z1nT[t * NROWS + i] = an;

    float dpos = block_sum_256((an - bn) * (an - bn), sbuf);

    if (t == 0) {
        g_sq[i] = s1 / (m1 * m1);
        g_spos[i] = logf(__expf(-0.5f * dpos) + EPS_F) + 1.0f;
    }
}

// ---------------------------------------------------------------------------
// kernel 2: fused Gram + exp + reduce over upper-triangular tiles
// grid = (64, 64), 256 threads. CTA (tj, ti) with tj >= ti computes the
// 128x128 block [ti*128.., tj*128..], sums exp(-0.5*d2) over it (minus the
// diagonal), weights off-diagonal tiles by 2 (symmetry), atomically adds.
// ---------------------------------------------------------------------------
__global__ void __launch_bounds__(256, 2) pair_kernel() {
    int ti = blockIdx.y;
    int tj = blockIdx.x;
    if (tj < ti) return;   // uniform per-block: safe with __syncthreads below

    __shared__ __align__(16) float As[BK][BM];
    __shared__ __align__(16) float Bs[BK][BM];
    __shared__ float red[8];

    int tid = threadIdx.x;
    int tx = tid & 15;     // 0..15 -> 8 output cols each
    int ty = tid >> 4;     // 0..15 -> 8 output rows each

    unsigned long long acc[8][4];
    #pragma unroll
    for (int r = 0; r < 8; ++r)
        #pragma unroll
        for (int c = 0; c < 4; ++c)
            acc[r][c] = 0ull;

    const float* baseA = g_z1nT + ti * BM;
    const float* baseB = g_z1nT + tj * BM;

    for (int kt = 0; kt < DIMS / BK; ++kt) {
        // load tiles: both are [k][i] slabs, fully coalesced float4
        #pragma unroll
        for (int r = 0; r < 4; ++r) {
            int idx  = tid + r * 256;          // 0..1023 float4 slots
            int krow = idx >> 5;               // 32 float4 per k-row
            int c4   = (idx & 31) << 2;
            const float* pa = baseA + (kt * BK + krow) * NROWS + c4;
            const float* pb = baseB + (kt * BK + krow) * NROWS + c4;
            *(float4*)&As[krow][c4] = *(const float4*)pa;
            *(float4*)&Bs[krow][c4] = *(const float4*)pb;
        }
        __syncthreads();

        #pragma unroll 4
        for (int kk = 0; kk < BK; ++kk) {
            float4 a0 = *(const float4*)&As[kk][ty * 8];
            float4 a1 = *(const float4*)&As[kk][ty * 8 + 4];
            const unsigned long long* Bp =
                (const unsigned long long*)&Bs[kk][tx * 8];
            unsigned long long b0 = Bp[0], b1 = Bp[1], b2 = Bp[2], b3 = Bp[3];

            unsigned long long ad[8];
            ad[0] = pack2(a0.x); ad[1] = pack2(a0.y);
            ad[2] = pack2(a0.z); ad[3] = pack2(a0.w);
            ad[4] = pack2(a1.x); ad[5] = pack2(a1.y);
            ad[6] = pack2(a1.z); ad[7] = pack2(a1.w);

            #pragma unroll
            for (int r = 0; r < 8; ++r) {
                fma2(acc[r][0], ad[r], b0);
                fma2(acc[r][1], ad[r], b1);
                fma2(acc[r][2], ad[r], b2);
                fma2(acc[r][3], ad[r], b3);
            }
        }
        __syncthreads();
    }

    // epilogue: d2 = max(sq_i + sq_j - 2*dot, 0); e = exp(-0.5*d2); mask diag
    float sqi[8], sqj[8];
    int gi0 = ti * BM + ty * 8;
    int gj0 = tj * BM + tx * 8;
    #pragma unroll
    for (int r = 0; r < 8; ++r) sqi[r] = g_sq[gi0 + r];
    #pragma unroll
    for (int c = 0; c < 8; ++c) sqj[c] = g_sq[gj0 + c];

    float sum = 0.f;
    #pragma unroll
    for (int r = 0; r < 8; ++r) {
        int gi = gi0 + r;
        #pragma unroll
        for (int c = 0; c < 4; ++c) {
            float d0, d1;
            unpack2(d0, d1, acc[r][c]);
            float dd0 = fmaxf(sqi[r] + sqj[2 * c]     - 2.0f * d0, 0.0f);
            float dd1 = fmaxf(sqi[r] + sqj[2 * c + 1] - 2.0f * d1, 0.0f);
            float e0 = __expf(-0.5f * dd0);
            float e1 = __expf(-0.5f * dd1);
            if (gi == gj0 + 2 * c)     e0 = 0.f;   // diagonal mask
            if (gi == gj0 + 2 * c + 1) e1 = 0.f;
            sum += e0 + e1;
        }
    }

    // block reduce + single atomic per CTA
    #pragma unroll
    for (int o = 16; o > 0; o >>= 1)
        sum += __shfl_xor_sync(0xffffffffu, sum, o);
    if ((tid & 31) == 0) red[tid >> 5] = sum;
    __syncthreads();
    if (tid == 0) {
        float s = 0.f;
        #pragma unroll
        for (int w = 0; w < 8; ++w) s += red[w];
        double contrib = (double)s;
        if (ti != tj) contrib *= 2.0;   // symmetric counterpart
        atomicAdd(&g_neg, contrib);
    }
}

// ---------------------------------------------------------------------------
// kernel 3: finalize -> scalar
// ---------------------------------------------------------------------------
__global__ void finalize_kernel(float* __restrict__ out) {
    __shared__ float sbuf[8];
    int t = threadIdx.x;
    float s = 0.f;
    for (int i = t; i < NROWS; i += 256) s += g_spos[i];
    float tot = block_sum_256(s, sbuf);
    if (t == 0) {
        double n = (double)NROWS;
        double mean_star = g_neg / (n * (n - 1.0)) + 1e-8;
        out[0] = (float)(-(double)tot / n + ALPHA_D * mean_star);
    }
}

// ---------------------------------------------------------------------------
extern "C" void kernel_launch(void* const* d_in, const int* in_sizes, int n_in,
                              void* d_out, int out_size) {
    const float* z1 = (const float*)d_in[0];
    const float* z2 = (const float*)d_in[1];
    float* out = (float*)d_out;

    zero_kernel<<<1, 1>>>();
    prep_kernel<<<NROWS, 256>>>(z1, z2);
    dim3 grid(NTILES, NTILES);
    pair_kernel<<<grid, 256>>>();
    finalize_kernel<<<1, 256>>>(out);
}

// round 4
// speedup vs baseline: 5.4762x; 5.4762x over previous
#include <cuda_runtime.h>
#include <cuda_bf16.h>
#include <math.h>

// Problem constants
#define NROWS 8192
#define DIMS  256
#define EPS_F 1e-8f

// Tiling
#define BM 128
#define BK 32
#define NTILES (NROWS / BM)   // 64

// Scratch (static device globals: allocation-free)
__device__ __nv_bfloat16 g_z1nb[NROWS * DIMS];  // normalized z1, row-major bf16
__device__ float  g_sq[NROWS];                  // fp32 sum-of-squares of normalized rows
__device__ float  g_spos[NROWS];                // per-row positive-pair score
__device__ double g_neg;                        // off-diagonal exp-sum accumulator

// ---------------------------------------------------------------------------
// helpers
// ---------------------------------------------------------------------------
__device__ __forceinline__ float block_sum_256(float v, float* sbuf) {
    #pragma unroll
    for (int o = 16; o > 0; o >>= 1)
        v += __shfl_xor_sync(0xffffffffu, v, o);
    int w = threadIdx.x >> 5;
    if ((threadIdx.x & 31) == 0) sbuf[w] = v;
    __syncthreads();
    float s = 0.f;
    #pragma unroll
    for (int i = 0; i < 8; ++i) s += sbuf[i];
    __syncthreads();
    return s;
}

// SMEM layout: row-major 128 x 32 bf16 (64B rows), XOR swizzle on 16B atoms.
// offset (in bf16 elems) for (row r, 16B-atom a): conflict-free for ldmatrix
// 8-row phases AND for cp.async 16B stores.
__device__ __forceinline__ int swz(int r, int atom) {
    return r * 32 + ((atom ^ ((r >> 1) & 3)) << 3);
}

// ---------------------------------------------------------------------------
__global__ void zero_kernel() { g_neg = 0.0; }

// ---------------------------------------------------------------------------
// prep: normalize rows, emit bf16 z1n (row-major), sq, s_pos
// grid = NROWS blocks, 256 threads (== DIMS)
// ---------------------------------------------------------------------------
__global__ void prep_kernel(const float* __restrict__ z1,
                            const float* __restrict__ z2) {
    __shared__ float sbuf[8];
    int i = blockIdx.x;
    int t = threadIdx.x;

    float a = z1[i * DIMS + t];
    float b = z2[i * DIMS + t];

    float s1 = block_sum_256(a * a, sbuf);
    float s2 = block_sum_256(b * b, sbuf);

    float m1 = fmaxf(sqrtf(s1), 1e-12f);
    float m2 = fmaxf(sqrtf(s2), 1e-12f);
    float an = a / m1;
    float bn = b / m2;

    g_z1nb[i * DIMS + t] = __float2bfloat16(an);

    float dpos = block_sum_256((an - bn) * (an - bn), sbuf);

    if (t == 0) {
        g_sq[i] = s1 / (m1 * m1);
        g_spos[i] = logf(__expf(-0.5f * dpos) + EPS_F) + 1.0f;
    }
}

// ---------------------------------------------------------------------------
// pair kernel: bf16 mma.sync Gram + exp + reduce, upper-triangular tiles.
// grid = (64, 64), 256 threads = 8 warps (2x4). CTA tile 128x128, warp 64x32.
// ---------------------------------------------------------------------------
__global__ void __launch_bounds__(256, 2) pair_kernel() {
    int ti = blockIdx.y;
    int tj = blockIdx.x;
    if (tj < ti) return;   // uniform per-CTA

    __shared__ __align__(16) __nv_bfloat16 As[2][BM * BK];
    __shared__ __align__(16) __nv_bfloat16 Bs[2][BM * BK];
    __shared__ float s_sq[256];
    __shared__ float red[8];

    int tid = threadIdx.x;
    int lane = tid & 31;
    int wid = tid >> 5;
    int wm = wid >> 2;   // 0..1  -> m offset wm*64
    int wn = wid & 3;    // 0..3  -> n offset wn*32

    const __nv_bfloat16* gA = g_z1nb + (size_t)ti * BM * DIMS;
    const __nv_bfloat16* gB = g_z1nb + (size_t)tj * BM * DIMS;

    // stage sq values for the epilogue
    if (tid < 128) s_sq[tid] = g_sq[ti * BM + tid];
    else           s_sq[tid] = g_sq[tj * BM + (tid - 128)];

    float acc[4][4][4];
    #pragma unroll
    for (int mt = 0; mt < 4; ++mt)
        #pragma unroll
        for (int nt = 0; nt < 4; ++nt)
            #pragma unroll
            for (int r = 0; r < 4; ++r)
                acc[mt][nt][r] = 0.f;

    auto issue = [&](int buf, int kt) {
        #pragma unroll
        for (int s = 0; s < 2; ++s) {
            int idx  = tid + (s << 8);      // 0..511
            int r    = idx >> 2;            // 0..127
            int atom = idx & 3;             // 0..3
            int off  = swz(r, atom);
            unsigned da = (unsigned)__cvta_generic_to_shared(&As[buf][off]);
            unsigned db = (unsigned)__cvta_generic_to_shared(&Bs[buf][off]);
            const __nv_bfloat16* sa = gA + r * DIMS + kt * BK + (atom << 3);
            const __nv_bfloat16* sb = gB + r * DIMS + kt * BK + (atom << 3);
            asm volatile("cp.async.cg.shared.global [%0], [%1], 16;\n"
                         :: "r"(da), "l"(sa));
            asm volatile("cp.async.cg.shared.global [%0], [%1], 16;\n"
                         :: "r"(db), "l"(sb));
        }
        asm volatile("cp.async.commit_group;\n");
    };

    issue(0, 0);

    int sel = lane >> 3;   // 0..3 (ldmatrix quadrant)
    int l7  = lane & 7;

    for (int kt = 0; kt < DIMS / BK; ++kt) {
        int buf = kt & 1;
        if (kt < DIMS / BK - 1) {
            issue(buf ^ 1, kt + 1);
            asm volatile("cp.async.wait_group 1;\n");
        } else {
            asm volatile("cp.async.wait_group 0;\n");
        }
        __syncthreads();

        #pragma unroll
        for (int kk = 0; kk < BK; kk += 16) {
            unsigned af[4][4];
            unsigned bf_[4][2];

            // A fragments: ldmatrix x4 per 16x16 m-tile
            #pragma unroll
            for (int mt = 0; mt < 4; ++mt) {
                int row  = wm * 64 + mt * 16 + ((sel & 1) << 3) + l7;
                int atom = (kk >> 3) + (sel >> 1);
                unsigned ad = (unsigned)__cvta_generic_to_shared(
                    &As[buf][swz(row, atom)]);
                asm volatile(
                    "ldmatrix.sync.aligned.m8n8.x4.shared.b16 "
                    "{%0,%1,%2,%3}, [%4];\n"
                    : "=r"(af[mt][0]), "=r"(af[mt][1]),
                      "=r"(af[mt][2]), "=r"(af[mt][3])
                    : "r"(ad));
            }
            // B fragments: one ldmatrix x4 covers two 8-col n-tiles
            #pragma unroll
            for (int np = 0; np < 2; ++np) {
                int row  = wn * 32 + np * 16 + ((sel >> 1) << 3) + l7;
                int atom = (kk >> 3) + (sel & 1);
                unsigned bd = (unsigned)__cvta_generic_to_shared(
                    &Bs[buf][swz(row, atom)]);
                asm volatile(
                    "ldmatrix.sync.aligned.m8n8.x4.shared.b16 "
                    "{%0,%1,%2,%3}, [%4];\n"
                    : "=r"(bf_[2 * np][0]), "=r"(bf_[2 * np][1]),
                      "=r"(bf_[2 * np + 1][0]), "=r"(bf_[2 * np + 1][1])
                    : "r"(bd));
            }

            #pragma unroll
            for (int mt = 0; mt < 4; ++mt)
                #pragma unroll
                for (int nt = 0; nt < 4; ++nt)
                    asm volatile(
                        "mma.sync.aligned.m16n8k16.row.col.f32.bf16.bf16.f32 "
                        "{%0,%1,%2,%3}, {%4,%5,%6,%7}, {%8,%9}, {%0,%1,%2,%3};\n"
                        : "+f"(acc[mt][nt][0]), "+f"(acc[mt][nt][1]),
                          "+f"(acc[mt][nt][2]), "+f"(acc[mt][nt][3])
                        : "r"(af[mt][0]), "r"(af[mt][1]),
                          "r"(af[mt][2]), "r"(af[mt][3]),
                          "r"(bf_[nt][0]), "r"(bf_[nt][1]));
        }
        __syncthreads();
    }

    // epilogue: d2 = max(sq_i + sq_j - 2*dot, 0); e = exp(-0.5*d2); mask diag
    int grow  = lane >> 2;
    int gcol2 = (lane & 3) << 1;
    float sum = 0.f;
    #pragma unroll
    for (int mt = 0; mt < 4; ++mt) {
        #pragma unroll
        for (int nt = 0; nt < 4; ++nt) {
            #pragma unroll
            for (int r = 0; r < 4; ++r) {
                int li = wm * 64 + mt * 16 + grow + ((r & 2) ? 8 : 0);
                int lj = wn * 32 + nt * 8 + gcol2 + (r & 1);
                float d2 = fmaxf(s_sq[li] + s_sq[128 + lj]
                                 - 2.0f * acc[mt][nt][r], 0.0f);
                float e = __expf(-0.5f * d2);
                if (ti * BM + li == tj * BM + lj) e = 0.f;
                sum += e;
            }
        }
    }

    // block reduce + single atomic per CTA
    #pragma unroll
    for (int o = 16; o > 0; o >>= 1)
        sum += __shfl_xor_sync(0xffffffffu, sum, o);
    if (lane == 0) red[wid] = sum;
    __syncthreads();
    if (tid == 0) {
        float s = 0.f;
        #pragma unroll
        for (int w = 0; w < 8; ++w) s += red[w];
        double contrib = (double)s;
        if (ti != tj) contrib *= 2.0;   // symmetric counterpart
        atomicAdd(&g_neg, contrib);
    }
}

// ---------------------------------------------------------------------------
__global__ void finalize_kernel(float* __restrict__ out) {
    __shared__ float sbuf[8];
    int t = threadIdx.x;
    float s = 0.f;
    for (int i = t; i < NROWS; i += 256) s += g_spos[i];
    float tot = block_sum_256(s, sbuf);
    if (t == 0) {
        double n = (double)NROWS;
        double mean_star = g_neg / (n * (n - 1.0)) + 1e-8;
        out[0] = (float)(-(double)tot / n + 1.5 * mean_star);
    }
}

// ---------------------------------------------------------------------------
extern "C" void kernel_launch(void* const* d_in, const int* in_sizes, int n_in,
                              void* d_out, int out_size) {
    const float* z1 = (const float*)d_in[0];
    const float* z2 = (const float*)d_in[1];
    float* out = (float*)d_out;

    zero_kernel<<<1, 1>>>();
    prep_kernel<<<NROWS, 256>>>(z1, z2);
    dim3 grid(NTILES, NTILES);
    pair_kernel<<<grid, 256>>>();
    finalize_kernel<<<1, 256>>>(out);
}